// round 8
// baseline (speedup 1.0000x reference)
#include <cuda_runtime.h>

#define HH 1024
#define WW 1024
#define NPTS 128
#define BIGD 16384        // sentinel 1D distance; BIGD^2 fits int

// Per-point results, padded to distinct 32B sectors (no hot-line contention).
__device__ volatile float g_loss[NPTS * 8];
__device__ volatile int   g_flag[NPTS * 8];   // zero-init; reset by block 0 each run

// One launch, no grid barrier, no single-address atomics.
// Block n = point n; thread = one row. Each thread scans the float map
// directly in a small window around pc, lazily extending (rare: P(miss in
// 8 cols) ~ 0.7^8 = 5.7% for 'on', ~0 for 'off').
__global__ void __launch_bounds__(1024, 1)
roadloss_kernel(const float* __restrict__ hd,
                const int*   __restrict__ pred,
                float*       __restrict__ out) {
    int n   = blockIdx.x;
    int tid = threadIdx.x;

    int pr = pred[2 * n];       // component 0: compared against rows in d2
    int pc = pred[2 * n + 1];   // component 1: compared against cols in d2

    // tid 0 prefetches the 4 neighbor values for the loss decision.
    // Reference indexes hd_map[py-1..py, px-1..px] with px=pred[:,0],
    // py=pred[:,1] (roles swapped vs the distance computation), JAX-clamped.
    float nv0 = 0.f, nv1 = 0.f, nv2 = 0.f, nv3 = 0.f;
    bool outside_frame = false;
    if (tid == 0) {
        int px = pr, py = pc;
        outside_frame = (px < 0) || (px > HH) || (py < 0) || (py > WW);
        int r0 = min(max(py - 1, 0), HH - 1);
        int r1 = min(max(py,     0), HH - 1);
        int c0 = min(max(px - 1, 0), WW - 1);
        int c1 = min(max(px,     0), WW - 1);
        nv0 = hd[r0 * WW + c0];
        nv1 = hd[r0 * WW + c1];
        nv2 = hd[r1 * WW + c0];
        nv3 = hd[r1 * WW + c1];
    }

    // ---- Per-row nearest on/off column scan ----
    int r = tid;
    const float4* rowp = reinterpret_cast<const float4*>(hd + r * WW);

    // Initial aligned 8-col window containing pc.
    int c0 = (pc - 4) & ~3;
    if (c0 < 0) c0 = 0;
    if (c0 > WW - 8) c0 = WW - 8;
    float4 a = rowp[(c0 >> 2)];
    float4 b = rowp[(c0 >> 2) + 1];

    int don = BIGD, doff = BIGD;
    {
        float w[8] = {a.x, a.y, a.z, a.w, b.x, b.y, b.z, b.w};
        #pragma unroll
        for (int j = 0; j < 8; j++) {
            int d = abs(c0 + j - pc);
            if (w[j] != 0.0f) don = min(don, d); else doff = min(doff, d);
        }
    }

    // Lazy extension: scan the nearer unscanned side one float4 at a time
    // until both mins are certified.
    // Invariants: L = c0-1 (== 3 mod 4), R = c0+8 (== 0 mod 4); both stay
    // aligned, so rowp indexing is always in-bounds when guarded.
    int L = c0 - 1;
    int R = c0 + 8;
    #pragma unroll 1
    while (true) {
        int bl = (L >= 0) ? (pc - L) : 0x3FFFFFFF;
        int br = (R < WW) ? (R - pc) : 0x3FFFFFFF;
        int bound = min(bl, br);
        if (don <= bound && doff <= bound) break;   // always true once both sides exhausted
        if (bl <= br) {
            float4 v = rowp[(L - 3) >> 2];        // cols [L-3, L]
            float w[4] = {v.x, v.y, v.z, v.w};
            int base = L - 3;
            #pragma unroll
            for (int j = 0; j < 4; j++) {
                int d = pc - (base + j);
                if (w[j] != 0.0f) don = min(don, d); else doff = min(doff, d);
            }
            L -= 4;
        } else {
            float4 v = rowp[R >> 2];              // cols [R, R+3]
            float w[4] = {v.x, v.y, v.z, v.w};
            #pragma unroll
            for (int j = 0; j < 4; j++) {
                int d = (R + j) - pc;
                if (w[j] != 0.0f) don = min(don, d); else doff = min(doff, d);
            }
            R += 4;
        }
    }

    int dr  = r - pr;
    int dr2 = dr * dr;
    int best_on  = dr2 + don * don;      // exact in int (< 2^21)
    int best_off = dr2 + doff * doff;

    // ---- Block min reduce ----
    best_on  = __reduce_min_sync(0xFFFFFFFFu, best_on);
    best_off = __reduce_min_sync(0xFFFFFFFFu, best_off);

    __shared__ int s_on[32];
    __shared__ int s_off[32];
    int wid  = tid >> 5;
    int lane = tid & 31;
    if (lane == 0) { s_on[wid] = best_on; s_off[wid] = best_off; }
    __syncthreads();
    if (wid == 0) {
        int av = __reduce_min_sync(0xFFFFFFFFu, s_on[lane]);
        int bv = __reduce_min_sync(0xFFFFFFFFu, s_off[lane]);
        if (lane == 0) {
            float loss = 0.0f;
            if (!outside_frame) {
                bool road = (nv0 == 1.0f) || (nv1 == 1.0f) ||
                            (nv2 == 1.0f) || (nv3 == 1.0f);
                const float K1 = 21.7f;
                const float LN2_OVER_K2 = 0.69314718055994531f / 40.0f;
                loss = road ? expf(sqrtf((float)bv) * LN2_OVER_K2)
                            : expf(-(float)av / K1);
            }
            g_loss[n * 8] = loss;         // volatile store (bypasses L1)
            __threadfence();              // loss globally visible before flag
            g_flag[n * 8] = 1;            // distinct 32B sector per block
        }
    }

    // ---- Block 0 aggregates: distributed polling, no atomics ----
    if (n == 0) {
        if (tid < NPTS) {
            while (g_flag[tid * 8] == 0) { __nanosleep(32); }
        }
        __syncthreads();
        __threadfence();                  // acquire: order g_loss reads after flags

        __shared__ float s_sum[NPTS];
        if (tid < NPTS) s_sum[tid] = g_loss[tid * 8];   // volatile load
        __syncthreads();
        if (tid < 64) s_sum[tid] += s_sum[tid + 64];
        __syncthreads();
        if (tid < 32) {
            float v = s_sum[tid] + s_sum[tid + 32];
            #pragma unroll
            for (int o = 16; o > 0; o >>= 1)
                v += __shfl_xor_sync(0xFFFFFFFFu, v, o);
            if (tid == 0) out[0] = v * (1.0f / (float)NPTS);
        }
        // Reset flags for the next graph replay (every flag was observed set
        // before this point, so all writers are done).
        if (tid < NPTS) g_flag[tid * 8] = 0;
    }
}

extern "C" void kernel_launch(void* const* d_in, const int* in_sizes, int n_in,
                              void* d_out, int out_size) {
    const float* hd  = (const float*)d_in[0];
    const int* pred  = (const int*)d_in[1];
    float* out       = (float*)d_out;
    roadloss_kernel<<<NPTS, 1024>>>(hd, pred, out);
}

// round 9
// speedup vs baseline: 1.0208x; 1.0208x over previous
#include <cuda_runtime.h>

#define HH 1024
#define WW 1024
#define NPTS 128
#define BIGD 16384        // sentinel 1D distance; BIGD^2 fits int

// Per-point results. Written by search_kernel, read by finalize_kernel.
// Kernel boundary is the synchronization — no fences/flags/atomics anywhere.
__device__ int g_on[NPTS];
__device__ int g_off[NPTS];

// ---------------------------------------------------------------------------
// Kernel A: per-point separable search, direct float map window scan.
// Block n = point n; thread = one row. Scans an aligned 8-col window around
// pc, lazily extending one float4 at a time until both nearest-on and
// nearest-off column distances are certified (rare: P(no on in 8 cols)
// ~ 0.7^8 = 5.7%; off ~ 0).
// ---------------------------------------------------------------------------
__global__ void __launch_bounds__(1024, 1)
search_kernel(const float* __restrict__ hd,
              const int*   __restrict__ pred) {
    int n   = blockIdx.x;
    int tid = threadIdx.x;

    int pr = pred[2 * n];       // component 0: compared against rows in d2
    int pc = pred[2 * n + 1];   // component 1: compared against cols in d2

    int r = tid;
    const float4* rowp = reinterpret_cast<const float4*>(hd + r * WW);

    // Initial aligned 8-col window containing pc.
    int c0 = (pc - 4) & ~3;
    if (c0 < 0) c0 = 0;
    if (c0 > WW - 8) c0 = WW - 8;
    float4 a = rowp[(c0 >> 2)];
    float4 b = rowp[(c0 >> 2) + 1];

    int don = BIGD, doff = BIGD;
    {
        float w[8] = {a.x, a.y, a.z, a.w, b.x, b.y, b.z, b.w};
        #pragma unroll
        for (int j = 0; j < 8; j++) {
            int d = abs(c0 + j - pc);
            if (w[j] != 0.0f) don = min(don, d); else doff = min(doff, d);
        }
    }

    // Lazy extension toward the nearer unscanned side.
    // Invariants: L == 3 (mod 4), R == 0 (mod 4) -> aligned, bounded accesses.
    int L = c0 - 1;
    int R = c0 + 8;
    #pragma unroll 1
    while (true) {
        int bl = (L >= 0) ? (pc - L) : 0x3FFFFFFF;
        int br = (R < WW) ? (R - pc) : 0x3FFFFFFF;
        int bound = min(bl, br);
        if (don <= bound && doff <= bound) break;   // guaranteed once both sides exhausted
        if (bl <= br) {
            float4 v = rowp[(L - 3) >> 2];          // cols [L-3, L]
            float w[4] = {v.x, v.y, v.z, v.w};
            int base = L - 3;
            #pragma unroll
            for (int j = 0; j < 4; j++) {
                int d = pc - (base + j);
                if (w[j] != 0.0f) don = min(don, d); else doff = min(doff, d);
            }
            L -= 4;
        } else {
            float4 v = rowp[R >> 2];                // cols [R, R+3]
            float w[4] = {v.x, v.y, v.z, v.w};
            #pragma unroll
            for (int j = 0; j < 4; j++) {
                int d = (R + j) - pc;
                if (w[j] != 0.0f) don = min(don, d); else doff = min(doff, d);
            }
            R += 4;
        }
    }

    int dr  = r - pr;
    int dr2 = dr * dr;
    int best_on  = dr2 + don * don;      // exact in int (< 2^21)
    int best_off = dr2 + doff * doff;

    // Block min reduce: REDUX within warp, shared across warps.
    best_on  = __reduce_min_sync(0xFFFFFFFFu, best_on);
    best_off = __reduce_min_sync(0xFFFFFFFFu, best_off);

    __shared__ int s_on[32];
    __shared__ int s_off[32];
    int wid  = tid >> 5;
    int lane = tid & 31;
    if (lane == 0) { s_on[wid] = best_on; s_off[wid] = best_off; }
    __syncthreads();
    if (wid == 0) {
        int av = __reduce_min_sync(0xFFFFFFFFu, s_on[lane]);
        int bv = __reduce_min_sync(0xFFFFFFFFu, s_off[lane]);
        if (lane == 0) {
            g_on[n]  = av;     // plain stores; kernel boundary synchronizes
            g_off[n] = bv;
        }
    }
}

// ---------------------------------------------------------------------------
// Kernel B: per-point loss + mean. Replicates the reference's swapped-index
// neighbor lookup (hd_map[py-1..py, px-1..px] with px=pred[:,0], py=pred[:,1])
// with JAX-style index clamping.
// ---------------------------------------------------------------------------
__global__ void finalize_kernel(const float* __restrict__ hd,
                                const int* __restrict__ pred,
                                float* __restrict__ out) {
    int n = threadIdx.x;   // 128 threads
    int px = pred[2 * n];
    int py = pred[2 * n + 1];
    bool outside_frame = (px < 0) || (px > HH) || (py < 0) || (py > WW);

    float loss = 0.0f;
    if (!outside_frame) {
        int r0 = min(max(py - 1, 0), HH - 1);
        int r1 = min(max(py,     0), HH - 1);
        int c0 = min(max(px - 1, 0), WW - 1);
        int c1 = min(max(px,     0), WW - 1);
        bool road = (hd[r0 * WW + c0] == 1.0f) || (hd[r0 * WW + c1] == 1.0f) ||
                    (hd[r1 * WW + c0] == 1.0f) || (hd[r1 * WW + c1] == 1.0f);
        float d2on  = (float)g_on[n];
        float d2off = (float)g_off[n];
        const float K1 = 21.7f;
        const float LN2_OVER_K2 = 0.69314718055994531f / 40.0f;
        loss = road ? expf(sqrtf(d2off) * LN2_OVER_K2)
                    : expf(-d2on / K1);
    }

    __shared__ float s[128];
    s[n] = loss;
    __syncthreads();
    if (n < 64) s[n] += s[n + 64];
    __syncthreads();
    if (n < 32) {
        float v = s[n] + s[n + 32];
        #pragma unroll
        for (int o = 16; o > 0; o >>= 1)
            v += __shfl_xor_sync(0xFFFFFFFFu, v, o);
        if (n == 0) out[0] = v * (1.0f / (float)NPTS);
    }
}

extern "C" void kernel_launch(void* const* d_in, const int* in_sizes, int n_in,
                              void* d_out, int out_size) {
    const float* hd  = (const float*)d_in[0];
    const int* pred  = (const int*)d_in[1];
    float* out       = (float*)d_out;

    search_kernel<<<NPTS, 1024>>>(hd, pred);
    finalize_kernel<<<1, 128>>>(hd, pred, out);
}